// round 1
// baseline (speedup 1.0000x reference)
#include <cuda_runtime.h>

#define BB 16
#define CC 256
#define HH 64
#define WW 64
#define SS 512
#define HW (HH*WW)

// Scratch (static __device__ arrays: allocation-free per harness rules)
__device__ float g_inter[BB*CC*HW];          // 256 MB intermediate activation
__device__ float g_style[BB*CC];
__device__ float g_demod[BB*CC];
__device__ float g_Rt[CC*CC];                // Rt[ci*CC + o] = sum_k W[o,ci,k]^2
__device__ float g_Wt[CC*9*CC];              // Wt[ci*9*CC + k*CC + o] = W[o,ci,k]

typedef unsigned long long u64;

__device__ __forceinline__ u64 ffma2(u64 a, u64 b, u64 c) {
    u64 d;
    asm("fma.rn.f32x2 %0, %1, %2, %3;" : "=l"(d) : "l"(a), "l"(b), "l"(c));
    return d;
}
__device__ __forceinline__ float f2lo(u64 v) { return __uint_as_float((unsigned)v); }
__device__ __forceinline__ float f2hi(u64 v) { return __uint_as_float((unsigned)(v >> 32)); }

// ---------------------------------------------------------------------------
// style[b,i] = (sum_s wv[b,s] * sw[i,s]) * (GAIN/sqrt(S)) + sb[i]
// GAIN * S^-0.5 = 2^-0.5 * 512^-0.5 = 1/32
// ---------------------------------------------------------------------------
__global__ void k_style(const float* __restrict__ wv,
                        const float* __restrict__ sw,
                        const float* __restrict__ sb) {
    __shared__ float s[SS];
    const int b = blockIdx.x, t = threadIdx.x;
    s[t]       = wv[b*SS + t];
    s[t + 256] = wv[b*SS + 256 + t];
    __syncthreads();
    float acc = 0.f;
    const float* rw = sw + t*SS;
    #pragma unroll 8
    for (int j = 0; j < SS; j++) acc += s[j] * rw[j];
    g_style[b*CC + t] = acc * 0.03125f + sb[t];
}

// ---------------------------------------------------------------------------
// Transpose W[o,ci,k] -> Wt[ci,k,o] and compute Rt[ci,o] = sum_k W^2
// grid = ci (256), threads = o (256): coalesced writes.
// ---------------------------------------------------------------------------
__global__ void k_prep(const float* __restrict__ w) {
    const int ci = blockIdx.x, o = threadIdx.x;
    const float* src = w + (o*CC + ci)*9;
    float s2 = 0.f;
    #pragma unroll
    for (int k = 0; k < 9; k++) {
        float v = src[k];
        s2 += v * v;
        g_Wt[ci*(9*CC) + k*CC + o] = v;
    }
    g_Rt[ci*CC + o] = s2;
}

// ---------------------------------------------------------------------------
// demod[b,o] = rsqrt(sum_i style[b,i]^2 * Rt[i,o] + 1e-8)
// ---------------------------------------------------------------------------
__global__ void k_demod() {
    __shared__ float st2[CC];
    const int b = blockIdx.x, t = threadIdx.x;
    float s = g_style[b*CC + t];
    st2[t] = s * s;
    __syncthreads();
    float acc = 0.f;
    #pragma unroll 8
    for (int i = 0; i < CC; i++) acc += st2[i] * g_Rt[i*CC + t];
    g_demod[b*CC + t] = rsqrtf(acc + 1e-8f);
}

// ---------------------------------------------------------------------------
// Modulated 3x3 conv (batch-shared weights) + demod + noise + leaky ReLU.
// Block: 8 output rows x 64 cols x 32 ocs. 256 threads.
// Thread: 8 cols x 8 ocs (4 f32x2 oc-pairs).
//   slot = tid & 63: r = slot & 7 (row), cg = slot >> 3 (col group, 8 cols)
//   g = tid >> 6: ocs = oc0 + g*8 .. +7
// Smem input tile is pre-splatted float2 (val,val), row stride 66 float2
// (132 floats == 4 mod 32 banks -> 2-way conflicts, bandwidth-optimal).
// Weight pairs are warp-broadcast LDS.64.
// in == nullptr -> read g_inter ; out == nullptr -> write g_inter.
// ---------------------------------------------------------------------------
__global__ __launch_bounds__(256, 2)
void k_conv(const float* __restrict__ in, float* __restrict__ out,
            const float* __restrict__ noise, const float* __restrict__ nw) {
    __shared__ __align__(16) float2 s_in[10*66];   // rows y0-1..y0+8, cols -1..64
    __shared__ __align__(16) float  s_w[9*32];     // [k][oc within block]
    __shared__ float s_style[CC];

    const float* inp = in  ? in  : g_inter;
    float*       outp = out ? out : g_inter;

    const int tid  = threadIdx.x;
    const int y0   = blockIdx.x * 8;
    const int oc0  = blockIdx.y * 32;
    const int b    = blockIdx.z;
    const int g    = tid >> 6;          // 0..3
    const int slot = tid & 63;
    const int r    = slot & 7;          // row in tile
    const int cg   = slot >> 3;         // col group
    const int x0   = cg * 8;            // first output col

    s_style[tid] = g_style[b*CC + tid];
    __syncthreads();

    u64 acc[4][8];
    #pragma unroll
    for (int p = 0; p < 4; p++)
        #pragma unroll
        for (int c = 0; c < 8; c++) acc[p][c] = 0ull;

    for (int ci = 0; ci < CC; ci++) {
        // ---- load input tile (scaled by style, splatted) ----
        {
            const float st = s_style[ci];
            const float* xin = inp + (b*CC + ci)*HW;
            #pragma unroll
            for (int it = 0; it < 3; it++) {
                int idx = tid + it*256;
                if (idx < 660) {
                    int row = idx / 66;
                    int col = idx - row*66;
                    int gy = y0 - 1 + row;
                    int gx = col - 1;
                    float v = 0.f;
                    if ((unsigned)gy < (unsigned)HH && (unsigned)gx < (unsigned)WW)
                        v = xin[gy*WW + gx] * st;
                    s_in[idx] = make_float2(v, v);
                }
            }
        }
        // ---- load weights for this ci: 9 k x 32 oc ----
        {
            int k = tid >> 5, o = tid & 31;
            s_w[tid] = g_Wt[ci*(9*CC) + k*CC + oc0 + o];
            if (tid < 32)
                s_w[256 + tid] = g_Wt[ci*(9*CC) + 8*CC + oc0 + tid];
        }
        __syncthreads();

        // ---- compute: 288 f32x2 FMAs ----
        #pragma unroll
        for (int dy = 0; dy < 3; dy++) {
            const u64* rp = (const u64*)(&s_in[(r + dy)*66 + x0]);
            u64 in2[10];
            #pragma unroll
            for (int j = 0; j < 10; j++) in2[j] = rp[j];
            #pragma unroll
            for (int dx = 0; dx < 3; dx++) {
                const int k = dy*3 + dx;
                const u64* wp = (const u64*)(&s_w[k*32 + g*8]);
                u64 w0 = wp[0], w1 = wp[1], w2 = wp[2], w3 = wp[3];
                #pragma unroll
                for (int c = 0; c < 8; c++) {
                    acc[0][c] = ffma2(in2[c + dx], w0, acc[0][c]);
                    acc[1][c] = ffma2(in2[c + dx], w1, acc[1][c]);
                    acc[2][c] = ffma2(in2[c + dx], w2, acc[2][c]);
                    acc[3][c] = ffma2(in2[c + dx], w3, acc[3][c]);
                }
            }
        }
        __syncthreads();
    }

    // ---- epilogue: demod, noise, leaky ReLU ----
    const int y = y0 + r;
    const float* np = noise + b*HW + y*WW + x0;
    float ns[8];
    #pragma unroll
    for (int c = 0; c < 8; c++) ns[c] = np[c];

    #pragma unroll
    for (int p = 0; p < 4; p++) {
        #pragma unroll
        for (int lane = 0; lane < 2; lane++) {
            const int oc = oc0 + g*8 + 2*p + lane;
            const float d  = g_demod[b*CC + oc];
            const float nv = nw[oc];
            float* op = outp + ((size_t)(b*CC + oc)*HH + y)*WW + x0;
            float vv[8];
            #pragma unroll
            for (int c = 0; c < 8; c++) {
                float v = lane ? f2hi(acc[p][c]) : f2lo(acc[p][c]);
                v = v * d + nv * ns[c];
                vv[c] = v > 0.f ? v : 0.2f * v;
            }
            *(float4*)op       = make_float4(vv[0], vv[1], vv[2], vv[3]);
            *(float4*)(op + 4) = make_float4(vv[4], vv[5], vv[6], vv[7]);
        }
    }
}

// ---------------------------------------------------------------------------
extern "C" void kernel_launch(void* const* d_in, const int* in_sizes, int n_in,
                              void* d_out, int out_size) {
    const float* x   = (const float*)d_in[0];
    const float* w1  = (const float*)d_in[1];
    const float* w2  = (const float*)d_in[2];
    const float* n1  = (const float*)d_in[3];
    const float* n2  = (const float*)d_in[4];
    const float* s1w = (const float*)d_in[5];
    const float* s1b = (const float*)d_in[6];
    const float* c1w = (const float*)d_in[7];
    const float* nw1 = (const float*)d_in[8];
    const float* s2w = (const float*)d_in[9];
    const float* s2b = (const float*)d_in[10];
    const float* c2w = (const float*)d_in[11];
    const float* nw2 = (const float*)d_in[12];
    float* out = (float*)d_out;

    dim3 cgrid(HH/8, CC/32, BB);   // 8 x 8 x 16 = 1024 blocks

    // stage 1
    k_style<<<BB, 256>>>(w1, s1w, s1b);
    k_prep <<<CC, 256>>>(c1w);
    k_demod<<<BB, 256>>>();
    k_conv <<<cgrid, 256>>>(x, nullptr, n1, nw1);

    // stage 2 (reuses style/demod/Wt scratch; stream order guarantees safety)
    k_style<<<BB, 256>>>(w2, s2w, s2b);
    k_prep <<<CC, 256>>>(c2w);
    k_demod<<<BB, 256>>>();
    k_conv <<<cgrid, 256>>>(nullptr, out, n2, nw2);
}

// round 2
// speedup vs baseline: 1.3545x; 1.3545x over previous
#include <cuda_runtime.h>

#define BB 16
#define CC 256
#define HH 64
#define WW 64
#define SS 512
#define HW (HH*WW)

// Scratch (static __device__ arrays: allocation-free per harness rules)
__device__ float g_inter[BB*CC*HW];          // intermediate activation
__device__ float g_style[BB*CC];
__device__ float g_demod[BB*CC];
__device__ float g_Rt[CC*CC];                // Rt[ci*CC + o] = sum_k W[o,ci,k]^2
__device__ float g_Wt[CC*9*CC];              // Wt[ci*9*CC + k*CC + o] = W[o,ci,k]

typedef unsigned long long u64;

__device__ __forceinline__ u64 ffma2(u64 a, u64 b, u64 c) {
    u64 d;
    asm("fma.rn.f32x2 %0, %1, %2, %3;" : "=l"(d) : "l"(a), "l"(b), "l"(c));
    return d;
}
__device__ __forceinline__ float f2lo(u64 v) { return __uint_as_float((unsigned)v); }
__device__ __forceinline__ float f2hi(u64 v) { return __uint_as_float((unsigned)(v >> 32)); }

// ---------------------------------------------------------------------------
// style[b,i] = (sum_s wv[b,s] * sw[i,s]) * (1/32) + sb[i]
// ---------------------------------------------------------------------------
__global__ void k_style(const float* __restrict__ wv,
                        const float* __restrict__ sw,
                        const float* __restrict__ sb) {
    __shared__ float s[SS];
    const int b = blockIdx.x, t = threadIdx.x;
    s[t]       = wv[b*SS + t];
    s[t + 256] = wv[b*SS + 256 + t];
    __syncthreads();
    float acc = 0.f;
    const float* rw = sw + t*SS;
    #pragma unroll 8
    for (int j = 0; j < SS; j++) acc += s[j] * rw[j];
    g_style[b*CC + t] = acc * 0.03125f + sb[t];
}

// ---------------------------------------------------------------------------
// Transpose W[o,ci,k] -> Wt[ci,k,o] and Rt[ci,o] = sum_k W^2
// ---------------------------------------------------------------------------
__global__ void k_prep(const float* __restrict__ w) {
    const int ci = blockIdx.x, o = threadIdx.x;
    const float* src = w + (o*CC + ci)*9;
    float s2 = 0.f;
    #pragma unroll
    for (int k = 0; k < 9; k++) {
        float v = src[k];
        s2 += v * v;
        g_Wt[ci*(9*CC) + k*CC + o] = v;
    }
    g_Rt[ci*CC + o] = s2;
}

// ---------------------------------------------------------------------------
// demod[b,o] = rsqrt(sum_i style[b,i]^2 * Rt[i,o] + 1e-8)
// ---------------------------------------------------------------------------
__global__ void k_demod() {
    __shared__ float st2[CC];
    const int b = blockIdx.x, t = threadIdx.x;
    float s = g_style[b*CC + t];
    st2[t] = s * s;
    __syncthreads();
    float acc = 0.f;
    #pragma unroll 8
    for (int i = 0; i < CC; i++) acc += st2[i] * g_Rt[i*CC + t];
    g_demod[b*CC + t] = rsqrtf(acc + 1e-8f);
}

// ---------------------------------------------------------------------------
// Modulated 3x3 conv (batch-shared weights, style folded into weights) +
// demod + noise + leaky ReLU.  Software-pipelined over ci with double-buffered
// smem and register staging of the next tile.
// Block: 8 rows x 64 cols x 32 ocs, 256 threads.
// Thread: 8 cols x 8 ocs (4 f32x2 oc-pairs).
// ---------------------------------------------------------------------------
__global__ __launch_bounds__(256, 2)
void k_conv(const float* __restrict__ in, float* __restrict__ out,
            const float* __restrict__ noise, const float* __restrict__ nw) {
    __shared__ __align__(16) float2 s_in[2][660];   // splatted raw x tile
    __shared__ __align__(16) float  s_w[2][292];    // style-scaled weights [k][oc]
    __shared__ float s_style[CC];

    const float* inp  = in  ? in  : g_inter;
    float*       outp = out ? out : g_inter;

    const int tid  = threadIdx.x;
    const int y0   = blockIdx.x * 8;
    const int oc0  = blockIdx.y * 32;
    const int b    = blockIdx.z;
    const int g    = tid >> 6;          // 0..3 (oc group)
    const int slot = tid & 63;
    const int r    = slot & 7;          // output row in tile
    const int cg   = slot >> 3;         // col group
    const int x0   = cg * 8;            // first output col

    s_style[tid] = g_style[b*CC + tid];

    // ---- hoisted per-thread load descriptors (negative offset == zero-fill)
    int goff0, goff1, goff2;
    {
        int idx = tid;
        int row = idx / 66, col = idx - row*66;
        int gy = y0 - 1 + row, gx = col - 1;
        goff0 = ((unsigned)gy < (unsigned)HH && (unsigned)gx < (unsigned)WW)
                    ? gy*WW + gx : -1;
        idx = tid + 256;
        row = idx / 66; col = idx - row*66;
        gy = y0 - 1 + row; gx = col - 1;
        goff1 = ((unsigned)gy < (unsigned)HH && (unsigned)gx < (unsigned)WW)
                    ? gy*WW + gx : -1;
        idx = tid + 512;
        row = idx / 66; col = idx - row*66;
        gy = y0 - 1 + row; gx = col - 1;
        goff2 = (idx < 660 && (unsigned)gy < (unsigned)HH && (unsigned)gx < (unsigned)WW)
                    ? gy*WW + gx : -1;
    }
    const int woff0 = (tid >> 5)*CC + oc0 + (tid & 31);
    const int woff1 = 8*CC + oc0 + tid;      // only threads < 32

    const float* xbase = inp + (size_t)(b*CC)*HW;

    float rv0, rv1, rv2, rw0, rw1;

#define LOADCI(ci_) do {                                                    \
        const float* p_ = xbase + (ci_)*HW;                                 \
        rv0 = (goff0 >= 0) ? __ldg(p_ + goff0) : 0.f;                       \
        rv1 = (goff1 >= 0) ? __ldg(p_ + goff1) : 0.f;                       \
        rv2 = (goff2 >= 0) ? __ldg(p_ + goff2) : 0.f;                       \
        const float* wp_ = g_Wt + (ci_)*(9*CC);                             \
        rw0 = wp_[woff0];                                                   \
        rw1 = (tid < 32) ? wp_[woff1] : 0.f;                                \
    } while (0)

#define STORECI(buf_, ci_) do {                                             \
        float st_ = s_style[ci_];                                           \
        s_in[buf_][tid]       = make_float2(rv0, rv0);                      \
        s_in[buf_][tid + 256] = make_float2(rv1, rv1);                      \
        if (tid < 148) s_in[buf_][tid + 512] = make_float2(rv2, rv2);       \
        s_w[buf_][tid] = rw0 * st_;                                         \
        if (tid < 32) s_w[buf_][256 + tid] = rw1 * st_;                     \
    } while (0)

#define COMPUTECI(buf_) do {                                                \
        _Pragma("unroll")                                                   \
        for (int dy = 0; dy < 3; dy++) {                                    \
            const u64* rp_ = (const u64*)(&s_in[buf_][(r + dy)*66 + x0]);   \
            u64 in2_[10];                                                   \
            _Pragma("unroll")                                               \
            for (int j = 0; j < 10; j++) in2_[j] = rp_[j];                  \
            _Pragma("unroll")                                               \
            for (int dx = 0; dx < 3; dx++) {                                \
                const int k_ = dy*3 + dx;                                   \
                const ulonglong2* wp_ =                                     \
                    (const ulonglong2*)(&s_w[buf_][k_*32 + g*8]);           \
                ulonglong2 wA_ = wp_[0], wB_ = wp_[1];                      \
                _Pragma("unroll")                                           \
                for (int c = 0; c < 8; c++) {                               \
                    acc[0][c] = ffma2(in2_[c + dx], wA_.x, acc[0][c]);      \
                    acc[1][c] = ffma2(in2_[c + dx], wA_.y, acc[1][c]);      \
                    acc[2][c] = ffma2(in2_[c + dx], wB_.x, acc[2][c]);      \
                    acc[3][c] = ffma2(in2_[c + dx], wB_.y, acc[3][c]);      \
                }                                                           \
            }                                                               \
        }                                                                   \
    } while (0)

    u64 acc[4][8];
    #pragma unroll
    for (int p = 0; p < 4; p++)
        #pragma unroll
        for (int c = 0; c < 8; c++) acc[p][c] = 0ull;

    __syncthreads();          // s_style visible
    LOADCI(0);

    for (int ci = 0; ci < CC; ci += 2) {
        STORECI(0, ci);
        __syncthreads();
        LOADCI(ci + 1);       // LDG latency hidden under COMPUTE(0)
        COMPUTECI(0);
        STORECI(1, ci + 1);
        __syncthreads();
        {
            int cn = (ci + 2 < CC) ? ci + 2 : CC - 1;   // tail: harmless reload
            LOADCI(cn);
        }
        COMPUTECI(1);
    }

#undef LOADCI
#undef STORECI
#undef COMPUTECI

    // ---- epilogue: demod, noise, leaky ReLU ----
    const int y = y0 + r;
    const float* np = noise + b*HW + y*WW + x0;
    float ns[8];
    #pragma unroll
    for (int c = 0; c < 8; c++) ns[c] = np[c];

    #pragma unroll
    for (int p = 0; p < 4; p++) {
        #pragma unroll
        for (int lane = 0; lane < 2; lane++) {
            const int oc = oc0 + g*8 + 2*p + lane;
            const float d  = g_demod[b*CC + oc];
            const float nv = nw[oc];
            float* op = outp + ((size_t)(b*CC + oc)*HH + y)*WW + x0;
            float vv[8];
            #pragma unroll
            for (int c = 0; c < 8; c++) {
                float v = lane ? f2hi(acc[p][c]) : f2lo(acc[p][c]);
                v = v * d + nv * ns[c];
                vv[c] = v > 0.f ? v : 0.2f * v;
            }
            *(float4*)op       = make_float4(vv[0], vv[1], vv[2], vv[3]);
            *(float4*)(op + 4) = make_float4(vv[4], vv[5], vv[6], vv[7]);
        }
    }
}

// ---------------------------------------------------------------------------
extern "C" void kernel_launch(void* const* d_in, const int* in_sizes, int n_in,
                              void* d_out, int out_size) {
    const float* x   = (const float*)d_in[0];
    const float* w1  = (const float*)d_in[1];
    const float* w2  = (const float*)d_in[2];
    const float* n1  = (const float*)d_in[3];
    const float* n2  = (const float*)d_in[4];
    const float* s1w = (const float*)d_in[5];
    const float* s1b = (const float*)d_in[6];
    const float* c1w = (const float*)d_in[7];
    const float* nw1 = (const float*)d_in[8];
    const float* s2w = (const float*)d_in[9];
    const float* s2b = (const float*)d_in[10];
    const float* c2w = (const float*)d_in[11];
    const float* nw2 = (const float*)d_in[12];
    float* out = (float*)d_out;

    dim3 cgrid(HH/8, CC/32, BB);   // 8 x 8 x 16 = 1024 blocks

    // stage 1
    k_style<<<BB, 256>>>(w1, s1w, s1b);
    k_prep <<<CC, 256>>>(c1w);
    k_demod<<<BB, 256>>>();
    k_conv <<<cgrid, 256>>>(x, nullptr, n1, nw1);

    // stage 2 (reuses style/demod/Wt scratch; stream order guarantees safety)
    k_style<<<BB, 256>>>(w2, s2w, s2b);
    k_prep <<<CC, 256>>>(c2w);
    k_demod<<<BB, 256>>>();
    k_conv <<<cgrid, 256>>>(nullptr, out, n2, nw2);
}